// round 2
// baseline (speedup 1.0000x reference)
#include <cuda_runtime.h>
#include <math.h>

// ---------------------------------------------------------------------------
// BDH block: B=2, T=2048, D=512, NH=8, N=256, 3 layers, fp32 throughout.
// ---------------------------------------------------------------------------

#define BM 64
#define BN 64
#define BK 16

constexpr int Bb = 2, Tt = 2048, Dd = 512, NHh = 8, Nn = 256;
constexpr int BT = Bb * Tt;        // 4096
constexpr int BH = Bb * NHh;       // 16
constexpr int HN = NHh * Nn;       // 2048
constexpr float LN_EPS = 1e-5f;
constexpr float TWO_PI = 6.283185307179586f;

// Scratch (device globals: no allocation allowed)
__device__ float g_xs   [(size_t)Bb * Tt * Dd];           // current residual stream
__device__ float g_tmp  [(size_t)Bb * Tt * Dd];           // in-proj pre-LN / yMLP
__device__ float g_xsp  [(size_t)BH * Tt * Nn];           // x_sparse (pre-rope)
__device__ float g_qr   [(size_t)BH * Tt * Nn];           // rope(x_sparse)
__device__ float g_ykv  [(size_t)BH * Tt * Dd];           // attention output (then LN'd in place)
__device__ float g_xy   [(size_t)Bb * Tt * NHh * Nn];     // gated sparse activations, [b,t,h,n]
__device__ float g_scores[(size_t)BH * Tt * Tt];          // causal scores (lower triangle only)

// ---------------------------------------------------------------------------
// Core 64x64 fp32 GEMM tile: 256 threads, 4x4 per thread, float4 smem paths.
// BNK=true  : B matrix is stored [n][k] row-major (multiply by B^T).
// BNK=false : B matrix is stored [k][n] row-major.
// ---------------------------------------------------------------------------
template <bool BNK>
__device__ __forceinline__ void gemm_tile(
    const float* __restrict__ A, int lda,
    const float* __restrict__ Bm, int ldb,
    int kCount, float acc[4][4])
{
    __shared__ float As[BK][BM];
    __shared__ float Bs[BK][BN];
    const int tid = threadIdx.x;
    const int tx = tid & 15, ty = tid >> 4;
    const int lrow = tid >> 2;            // 0..63
    const int lseg = (tid & 3) << 2;      // 0,4,8,12

    for (int k0 = 0; k0 < kCount; k0 += BK) {
        {
            float4 v = *(const float4*)(A + (size_t)lrow * lda + k0 + lseg);
            As[lseg + 0][lrow] = v.x; As[lseg + 1][lrow] = v.y;
            As[lseg + 2][lrow] = v.z; As[lseg + 3][lrow] = v.w;
        }
        if (BNK) {
            float4 v = *(const float4*)(Bm + (size_t)lrow * ldb + k0 + lseg);
            Bs[lseg + 0][lrow] = v.x; Bs[lseg + 1][lrow] = v.y;
            Bs[lseg + 2][lrow] = v.z; Bs[lseg + 3][lrow] = v.w;
        } else {
            int r = tid >> 4;             // 0..15
            int c = (tid & 15) << 2;      // 0..60
            float4 v = *(const float4*)(Bm + (size_t)(k0 + r) * ldb + c);
            *(float4*)&Bs[r][c] = v;
        }
        __syncthreads();
        #pragma unroll
        for (int k = 0; k < BK; k++) {
            float4 a = *(const float4*)&As[k][ty << 2];
            float4 b = *(const float4*)&Bs[k][tx << 2];
            acc[0][0] += a.x * b.x; acc[0][1] += a.x * b.y; acc[0][2] += a.x * b.z; acc[0][3] += a.x * b.w;
            acc[1][0] += a.y * b.x; acc[1][1] += a.y * b.y; acc[1][2] += a.y * b.z; acc[1][3] += a.y * b.w;
            acc[2][0] += a.z * b.x; acc[2][1] += a.z * b.y; acc[2][2] += a.z * b.z; acc[2][3] += a.z * b.w;
            acc[3][0] += a.w * b.x; acc[3][1] += a.w * b.y; acc[3][2] += a.w * b.z; acc[3][3] += a.w * b.w;
        }
        __syncthreads();
    }
}

// ---------------------------------------------------------------------------
// Block-wide pair reduction (sum, sumsq) over 256 threads.
// ---------------------------------------------------------------------------
__device__ __forceinline__ void block_sum2(float& s, float& q)
{
    __shared__ float shs[8], shq[8];
    __syncthreads();   // protect smem reuse across consecutive calls
    #pragma unroll
    for (int o = 16; o > 0; o >>= 1) {
        s += __shfl_xor_sync(0xffffffffu, s, o);
        q += __shfl_xor_sync(0xffffffffu, q, o);
    }
    int w = threadIdx.x >> 5;
    if ((threadIdx.x & 31) == 0) { shs[w] = s; shq[w] = q; }
    __syncthreads();
    s = 0.f; q = 0.f;
    #pragma unroll
    for (int i = 0; i < 8; i++) { s += shs[i]; q += shq[i]; }
}

// LN over 512 elems held as (v0, v1) per thread (256 threads).
__device__ __forceinline__ void ln512_pair(float v0, float v1, float& o0, float& o1)
{
    float s = v0 + v1, q = v0 * v0 + v1 * v1;
    block_sum2(s, q);
    float mu  = s * (1.f / 512.f);
    float var = q * (1.f / 512.f) - mu * mu;
    float r   = rsqrtf(var + LN_EPS);
    o0 = (v0 - mu) * r;
    o1 = (v1 - mu) * r;
}

// ---------------------------------------------------------------------------
// Kernels
// ---------------------------------------------------------------------------

// in-projection: g_tmp = x @ w_in + b_in     (4096 x 512) @ (512 x 512)
__global__ __launch_bounds__(256) void k_inproj(
    const float* __restrict__ x, const float* __restrict__ w, const float* __restrict__ bias)
{
    int n0 = blockIdx.x * BN, m0 = blockIdx.y * BM;
    float acc[4][4] = {};
    gemm_tile<false>(x + (size_t)m0 * Dd, Dd, w + n0, Dd, Dd, acc);
    int tx = threadIdx.x & 15, ty = threadIdx.x >> 4;
    #pragma unroll
    for (int i = 0; i < 4; i++) {
        int m = m0 + (ty << 2) + i;
        #pragma unroll
        for (int j = 0; j < 4; j++) {
            int n = n0 + (tx << 2) + j;
            g_tmp[(size_t)m * Dd + n] = acc[i][j] + bias[n];
        }
    }
}

__global__ __launch_bounds__(256) void k_ln_inproj()
{
    size_t row = blockIdx.x;
    const float* p = g_tmp + row * 512;
    int t = threadIdx.x;
    float o0, o1;
    ln512_pair(p[t], p[t + 256], o0, o1);
    g_xs[row * 512 + t] = o0;
    g_xs[row * 512 + t + 256] = o1;
}

// encode + relu + rope: per (b,h):  x_sparse = relu(xs @ enc[h]);  QR = rope(x_sparse)
__global__ __launch_bounds__(256) void k_enc_rope(const float* __restrict__ enc)
{
    int z = blockIdx.z;                       // b*NH + h
    int b = z / NHh, h = z % NHh;
    int n0 = blockIdx.x * BN, m0 = blockIdx.y * BM;
    const float* A  = g_xs + (size_t)b * Tt * Dd + (size_t)m0 * Dd;
    const float* Bm = enc + (size_t)h * Dd * Nn + n0;
    float acc[4][4] = {};
    gemm_tile<false>(A, Dd, Bm, Nn, Dd, acc);
    int tx = threadIdx.x & 15, ty = threadIdx.x >> 4;
    #pragma unroll
    for (int i = 0; i < 4; i++) {
        int t = m0 + (ty << 2) + i;
        size_t rowbase = ((size_t)z * Tt + t) * Nn;
        #pragma unroll
        for (int p = 0; p < 2; p++) {
            int c = n0 + (tx << 2) + p * 2;   // even column: start of a rope pair
            float v0 = fmaxf(acc[i][p * 2], 0.f);
            float v1 = fmaxf(acc[i][p * 2 + 1], 0.f);
            // freq = THETA^(-q/N) / (2pi), THETA=2^16, N=256 => exp2(-q/16)/(2pi)
            float freq = exp2f((float)c * (-1.f / 16.f)) * (1.f / TWO_PI);
            float ph = (float)t * freq;
            ph = (ph - floorf(ph)) * TWO_PI;
            float sp, cp;
            sincosf(ph, &sp, &cp);
            g_xsp[rowbase + c]     = v0;
            g_xsp[rowbase + c + 1] = v1;
            g_qr[rowbase + c]      = v0 * cp - v1 * sp;
            g_qr[rowbase + c + 1]  = v1 * cp + v0 * sp;
        }
    }
}

// scores = QR @ QR^T, strict-lower causal; only tiles with s_tile <= t_tile computed.
__global__ __launch_bounds__(256) void k_qk()
{
    int stile = blockIdx.x, ttile = blockIdx.y, z = blockIdx.z;
    if (stile > ttile) return;
    const float* Q  = g_qr + ((size_t)z * Tt + (size_t)ttile * BM) * Nn;
    const float* Kp = g_qr + ((size_t)z * Tt + (size_t)stile * BN) * Nn;
    float acc[4][4] = {};
    gemm_tile<true>(Q, Nn, Kp, Nn, Nn, acc);
    int tx = threadIdx.x & 15, ty = threadIdx.x >> 4;
    #pragma unroll
    for (int i = 0; i < 4; i++) {
        int t = ttile * BM + (ty << 2) + i;
        #pragma unroll
        for (int j = 0; j < 4; j++) {
            int s = stile * BN + (tx << 2) + j;
            g_scores[((size_t)z * Tt + t) * Tt + s] = (t > s) ? acc[i][j] : 0.f;
        }
    }
}

// yKV = scores @ xs  (V = xs, head-broadcast). K extent = (t_tile+1)*64 (causal).
__global__ __launch_bounds__(256) void k_sv()
{
    int dtile = blockIdx.x, ttile = blockIdx.y, z = blockIdx.z;
    int b = z / NHh;
    const float* A  = g_scores + ((size_t)z * Tt + (size_t)ttile * BM) * Tt;
    const float* Bm = g_xs + (size_t)b * Tt * Dd + dtile * BN;
    float acc[4][4] = {};
    gemm_tile<false>(A, Tt, Bm, Dd, (ttile + 1) * BM, acc);
    int tx = threadIdx.x & 15, ty = threadIdx.x >> 4;
    #pragma unroll
    for (int i = 0; i < 4; i++) {
        int t = ttile * BM + (ty << 2) + i;
        #pragma unroll
        for (int j = 0; j < 4; j++) {
            int d = dtile * BN + (tx << 2) + j;
            g_ykv[((size_t)z * Tt + t) * Dd + d] = acc[i][j];
        }
    }
}

// LN over d of yKV (in place). One block per (z,t) row.
__global__ __launch_bounds__(256) void k_ln_ykv()
{
    size_t row = blockIdx.x;
    float* p = g_ykv + row * 512;
    int t = threadIdx.x;
    float v0 = p[t], v1 = p[t + 256];
    float o0, o1;
    ln512_pair(v0, v1, o0, o1);
    p[t] = o0;
    p[t + 256] = o1;
}

// y_sparse = relu(ln(yKV) @ encv[h]); xy = x_sparse * y_sparse  -> layout [b,t,h,n]
__global__ __launch_bounds__(256) void k_venc_mul(const float* __restrict__ encv)
{
    int z = blockIdx.z;
    int b = z / NHh, h = z % NHh;
    int n0 = blockIdx.x * BN, m0 = blockIdx.y * BM;
    const float* A  = g_ykv + (size_t)z * Tt * Dd + (size_t)m0 * Dd;
    const float* Bm = encv + (size_t)h * Dd * Nn + n0;
    float acc[4][4] = {};
    gemm_tile<false>(A, Dd, Bm, Nn, Dd, acc);
    int tx = threadIdx.x & 15, ty = threadIdx.x >> 4;
    #pragma unroll
    for (int i = 0; i < 4; i++) {
        int t = m0 + (ty << 2) + i;
        size_t src = ((size_t)z * Tt + t) * Nn;
        size_t dst = (((size_t)(b * Tt + t)) * NHh + h) * Nn;
        #pragma unroll
        for (int j = 0; j < 4; j++) {
            int n = n0 + (tx << 2) + j;
            float y = fmaxf(acc[i][j], 0.f);
            g_xy[dst + n] = y * g_xsp[src + n];
        }
    }
}

// yMLP = xy[4096, 2048] @ decoder[2048, 512] -> g_tmp
__global__ __launch_bounds__(256) void k_dec(const float* __restrict__ decw)
{
    int n0 = blockIdx.x * BN, m0 = blockIdx.y * BM;
    const float* A = g_xy + (size_t)m0 * HN;
    float acc[4][4] = {};
    gemm_tile<false>(A, HN, decw + n0, Dd, HN, acc);
    int tx = threadIdx.x & 15, ty = threadIdx.x >> 4;
    #pragma unroll
    for (int i = 0; i < 4; i++) {
        int m = m0 + (ty << 2) + i;
        #pragma unroll
        for (int j = 0; j < 4; j++) {
            int n = n0 + (tx << 2) + j;
            g_tmp[(size_t)m * Dd + n] = acc[i][j];
        }
    }
}

// xs = ln(x_res + ln(yMLP))  (per 512-wide row, in place on g_xs)
__global__ __launch_bounds__(256) void k_resid_ln()
{
    size_t row = blockIdx.x;
    const float* a = g_xs + row * 512;
    const float* bp = g_tmp + row * 512;
    int t = threadIdx.x;
    float l0, l1;
    ln512_pair(bp[t], bp[t + 256], l0, l1);
    float t0 = a[t] + l0, t1 = a[t + 256] + l1;
    float o0, o1;
    ln512_pair(t0, t1, o0, o1);
    g_xs[row * 512 + t] = o0;
    g_xs[row * 512 + t + 256] = o1;
}

// logits = xs @ head_w + head_b -> d_out
__global__ __launch_bounds__(256) void k_head(
    const float* __restrict__ hw, const float* __restrict__ hb, float* __restrict__ out)
{
    int n0 = blockIdx.x * BN, m0 = blockIdx.y * BM;
    const float* A = g_xs + (size_t)m0 * Dd;
    float acc[4][4] = {};
    gemm_tile<false>(A, Dd, hw + n0, Dd, Dd, acc);
    int tx = threadIdx.x & 15, ty = threadIdx.x >> 4;
    #pragma unroll
    for (int i = 0; i < 4; i++) {
        int m = m0 + (ty << 2) + i;
        #pragma unroll
        for (int j = 0; j < 4; j++) {
            int n = n0 + (tx << 2) + j;
            out[(size_t)m * Dd + n] = acc[i][j] + hb[n];
        }
    }
}

// ---------------------------------------------------------------------------
extern "C" void kernel_launch(void* const* d_in, const int* in_sizes, int n_in,
                              void* d_out, int out_size)
{
    const float* x    = (const float*)d_in[0];
    const float* w_in = (const float*)d_in[1];
    const float* b_in = (const float*)d_in[2];
    const float* enc  = (const float*)d_in[3];
    const float* encv = (const float*)d_in[4];
    const float* dec  = (const float*)d_in[5];
    const float* hw   = (const float*)d_in[6];
    const float* hb   = (const float*)d_in[7];
    float* out = (float*)d_out;

    dim3 blk(256);

    k_inproj<<<dim3(Dd / BN, BT / BM), blk>>>(x, w_in, b_in);
    k_ln_inproj<<<BT, 256>>>();

    for (int layer = 0; layer < 3; layer++) {
        k_enc_rope<<<dim3(Nn / BN, Tt / BM, BH), blk>>>(enc);
        k_qk<<<dim3(Tt / BN, Tt / BM, BH), blk>>>();
        k_sv<<<dim3(Dd / BN, Tt / BM, BH), blk>>>();
        k_ln_ykv<<<BH * Tt, 256>>>();
        k_venc_mul<<<dim3(Nn / BN, Tt / BM, BH), blk>>>(encv);
        k_dec<<<dim3(Dd / BN, BT / BM), blk>>>(dec);
        k_resid_ln<<<BT, 256>>>();
    }

    k_head<<<dim3(Dd / BN, BT / BM), blk>>>(hw, hb, out);
}

// round 3
// speedup vs baseline: 2.2965x; 2.2965x over previous
#include <cuda_runtime.h>
#include <math.h>
#include <stdint.h>

// ---------------------------------------------------------------------------
// BDH block: B=2, T=2048, D=512, NH=8, N=256, 3 layers.
// GEMMs on tf32 tensor cores (mma.sync m16n8k8), fp32 accumulate.
// ---------------------------------------------------------------------------

constexpr int Bb = 2, Tt = 2048, Dd = 512, NHh = 8, Nn = 256;
constexpr int BT = Bb * Tt;        // 4096
constexpr int BH = Bb * NHh;       // 16
constexpr int HN = NHh * Nn;       // 2048
constexpr float LN_EPS = 1e-5f;
constexpr float TWO_PI = 6.283185307179586f;

#define BMT 128
#define BNT 128
#define BKT 32

// Scratch (device globals: no allocation allowed)
__device__ float g_xs   [(size_t)Bb * Tt * Dd];
__device__ float g_tmp  [(size_t)Bb * Tt * Dd];
__device__ float g_xsp  [(size_t)BH * Tt * Nn];
__device__ float g_qr   [(size_t)BH * Tt * Nn];
__device__ float g_ykv  [(size_t)BH * Tt * Dd];
__device__ float g_xy   [(size_t)Bb * Tt * NHh * Nn];
__device__ float g_scores[(size_t)BH * Tt * Tt];

__device__ __forceinline__ uint32_t f2tf(float f)
{
    uint32_t u;
    asm("cvt.rna.tf32.f32 %0, %1;" : "=r"(u) : "f"(f));
    return u;
}

// ---------------------------------------------------------------------------
// 128x128 tf32 MMA tile. 256 threads = 8 warps in 2(m) x 4(n) grid;
// each warp owns 64x32 = 4x4 m16n8k8 fragments. smem K-major, pad 132.
// BNK=true : B stored [n][k] row-major (B^T multiply).
// BNK=false: B stored [k][n] row-major.
// acc[mi][nj][e]: e mapping: {(r, c), (r, c+1), (r+8, c), (r+8, c+1)}
//   with r = lane>>2, c = (lane&3)*2, inside fragment (mi*16, nj*8).
// ---------------------------------------------------------------------------
template <bool BNK>
__device__ __forceinline__ void mma_tile128(
    const float* __restrict__ A, int lda,
    const float* __restrict__ Bm, int ldb,
    int kCount, float acc[4][4][4])
{
    __shared__ uint32_t As[BKT][BMT + 4];
    __shared__ uint32_t Bs[BKT][BNT + 4];
    const int tid = threadIdx.x;
    const int lane = tid & 31, warp = tid >> 5;
    const int am = (warp >> 2) * 64;       // warp m offset
    const int bn = (warp & 3) * 32;        // warp n offset
    const int ar = lane >> 2, ac = lane & 3;

    for (int k0 = 0; k0 < kCount; k0 += BKT) {
        // A: 128 x 32, transpose into As[k][m]
        #pragma unroll
        for (int l = 0; l < 4; l++) {
            int idx = tid + l * 256;
            int m = idx >> 3, seg = (idx & 7) << 2;
            float4 v = *(const float4*)(A + (size_t)m * lda + k0 + seg);
            As[seg + 0][m] = f2tf(v.x);
            As[seg + 1][m] = f2tf(v.y);
            As[seg + 2][m] = f2tf(v.z);
            As[seg + 3][m] = f2tf(v.w);
        }
        if (BNK) {
            #pragma unroll
            for (int l = 0; l < 4; l++) {
                int idx = tid + l * 256;
                int n = idx >> 3, seg = (idx & 7) << 2;
                float4 v = *(const float4*)(Bm + (size_t)n * ldb + k0 + seg);
                Bs[seg + 0][n] = f2tf(v.x);
                Bs[seg + 1][n] = f2tf(v.y);
                Bs[seg + 2][n] = f2tf(v.z);
                Bs[seg + 3][n] = f2tf(v.w);
            }
        } else {
            #pragma unroll
            for (int l = 0; l < 4; l++) {
                int idx = tid + l * 256;
                int k = idx >> 5, nseg = (idx & 31) << 2;
                float4 v = *(const float4*)(Bm + (size_t)(k0 + k) * ldb + nseg);
                Bs[k][nseg + 0] = f2tf(v.x);
                Bs[k][nseg + 1] = f2tf(v.y);
                Bs[k][nseg + 2] = f2tf(v.z);
                Bs[k][nseg + 3] = f2tf(v.w);
            }
        }
        __syncthreads();

        #pragma unroll
        for (int kk = 0; kk < BKT; kk += 8) {
            uint32_t a[4][4], b[4][2];
            #pragma unroll
            for (int mi = 0; mi < 4; mi++) {
                int mb = am + mi * 16 + ar;
                a[mi][0] = As[kk + ac][mb];
                a[mi][1] = As[kk + ac][mb + 8];
                a[mi][2] = As[kk + ac + 4][mb];
                a[mi][3] = As[kk + ac + 4][mb + 8];
            }
            #pragma unroll
            for (int nj = 0; nj < 4; nj++) {
                int nb = bn + nj * 8 + ar;
                b[nj][0] = Bs[kk + ac][nb];
                b[nj][1] = Bs[kk + ac + 4][nb];
            }
            #pragma unroll
            for (int mi = 0; mi < 4; mi++)
                #pragma unroll
                for (int nj = 0; nj < 4; nj++)
                    asm volatile(
                        "mma.sync.aligned.m16n8k8.row.col.f32.tf32.tf32.f32 "
                        "{%0,%1,%2,%3}, {%4,%5,%6,%7}, {%8,%9}, {%0,%1,%2,%3};"
                        : "+f"(acc[mi][nj][0]), "+f"(acc[mi][nj][1]),
                          "+f"(acc[mi][nj][2]), "+f"(acc[mi][nj][3])
                        : "r"(a[mi][0]), "r"(a[mi][1]), "r"(a[mi][2]), "r"(a[mi][3]),
                          "r"(b[nj][0]), "r"(b[nj][1]));
        }
        __syncthreads();
    }
}

// Epilogue index helpers
#define EPI_SETUP \
    const int lane = threadIdx.x & 31, warp = threadIdx.x >> 5; \
    const int am = (warp >> 2) * 64, bn = (warp & 3) * 32; \
    const int er = lane >> 2, ec = (lane & 3) * 2;

// ---------------------------------------------------------------------------
// LN helpers (unchanged from R1)
// ---------------------------------------------------------------------------
__device__ __forceinline__ void block_sum2(float& s, float& q)
{
    __shared__ float shs[8], shq[8];
    __syncthreads();
    #pragma unroll
    for (int o = 16; o > 0; o >>= 1) {
        s += __shfl_xor_sync(0xffffffffu, s, o);
        q += __shfl_xor_sync(0xffffffffu, q, o);
    }
    int w = threadIdx.x >> 5;
    if ((threadIdx.x & 31) == 0) { shs[w] = s; shq[w] = q; }
    __syncthreads();
    s = 0.f; q = 0.f;
    #pragma unroll
    for (int i = 0; i < 8; i++) { s += shs[i]; q += shq[i]; }
}

__device__ __forceinline__ void ln512_pair(float v0, float v1, float& o0, float& o1)
{
    float s = v0 + v1, q = v0 * v0 + v1 * v1;
    block_sum2(s, q);
    float mu  = s * (1.f / 512.f);
    float var = q * (1.f / 512.f) - mu * mu;
    float r   = rsqrtf(var + LN_EPS);
    o0 = (v0 - mu) * r;
    o1 = (v1 - mu) * r;
}

// ---------------------------------------------------------------------------
// Kernels
// ---------------------------------------------------------------------------

__global__ __launch_bounds__(256, 2) void k_inproj(
    const float* __restrict__ x, const float* __restrict__ w, const float* __restrict__ bias)
{
    int n0 = blockIdx.x * BNT, m0 = blockIdx.y * BMT;
    float acc[4][4][4] = {};
    mma_tile128<false>(x + (size_t)m0 * Dd, Dd, w + n0, Dd, Dd, acc);
    EPI_SETUP;
    #pragma unroll
    for (int mi = 0; mi < 4; mi++)
        #pragma unroll
        for (int nj = 0; nj < 4; nj++) {
            int m = m0 + am + mi * 16 + er;
            int n = n0 + bn + nj * 8 + ec;
            g_tmp[(size_t)m * Dd + n]           = acc[mi][nj][0] + bias[n];
            g_tmp[(size_t)m * Dd + n + 1]       = acc[mi][nj][1] + bias[n + 1];
            g_tmp[(size_t)(m + 8) * Dd + n]     = acc[mi][nj][2] + bias[n];
            g_tmp[(size_t)(m + 8) * Dd + n + 1] = acc[mi][nj][3] + bias[n + 1];
        }
}

__global__ __launch_bounds__(256) void k_ln_inproj()
{
    size_t row = blockIdx.x;
    const float* p = g_tmp + row * 512;
    int t = threadIdx.x;
    float o0, o1;
    ln512_pair(p[t], p[t + 256], o0, o1);
    g_xs[row * 512 + t] = o0;
    g_xs[row * 512 + t + 256] = o1;
}

// encode + relu + rope. ec is always even -> each (e0,e1)/(e2,e3) is a rope pair.
__global__ __launch_bounds__(256, 2) void k_enc_rope(const float* __restrict__ enc)
{
    int z = blockIdx.z;
    int b = z / NHh, h = z % NHh;
    int n0 = blockIdx.x * BNT, m0 = blockIdx.y * BMT;
    const float* A  = g_xs + (size_t)b * Tt * Dd + (size_t)m0 * Dd;
    const float* Bm = enc + (size_t)h * Dd * Nn + n0;
    float acc[4][4][4] = {};
    mma_tile128<false>(A, Dd, Bm, Nn, Dd, acc);
    EPI_SETUP;
    #pragma unroll
    for (int mi = 0; mi < 4; mi++)
        #pragma unroll
        for (int nj = 0; nj < 4; nj++) {
            int ne = n0 + bn + nj * 8 + ec;   // even column (rope pair start)
            float freq = exp2f((float)ne * (-1.f / 16.f)) * (1.f / TWO_PI);
            #pragma unroll
            for (int hh = 0; hh < 2; hh++) {
                int t = m0 + am + mi * 16 + er + hh * 8;
                float v0 = fmaxf(acc[mi][nj][hh * 2], 0.f);
                float v1 = fmaxf(acc[mi][nj][hh * 2 + 1], 0.f);
                float ph = (float)t * freq;
                ph = (ph - floorf(ph)) * TWO_PI;
                float sp, cp;
                sincosf(ph, &sp, &cp);
                size_t base = ((size_t)z * Tt + t) * Nn + ne;
                g_xsp[base]     = v0;
                g_xsp[base + 1] = v1;
                g_qr[base]      = v0 * cp - v1 * sp;
                g_qr[base + 1]  = v1 * cp + v0 * sp;
            }
        }
}

// scores = QR @ QR^T, strict-lower causal
__global__ __launch_bounds__(256, 2) void k_qk()
{
    int stile = blockIdx.x, ttile = blockIdx.y, z = blockIdx.z;
    if (stile > ttile) return;
    const float* Q  = g_qr + ((size_t)z * Tt + (size_t)ttile * BMT) * Nn;
    const float* Kp = g_qr + ((size_t)z * Tt + (size_t)stile * BNT) * Nn;
    float acc[4][4][4] = {};
    mma_tile128<true>(Q, Nn, Kp, Nn, Nn, acc);
    EPI_SETUP;
    #pragma unroll
    for (int mi = 0; mi < 4; mi++)
        #pragma unroll
        for (int nj = 0; nj < 4; nj++) {
            int t = ttile * BMT + am + mi * 16 + er;
            int s = stile * BNT + bn + nj * 8 + ec;
            size_t r0 = ((size_t)z * Tt + t) * Tt;
            size_t r1 = ((size_t)z * Tt + t + 8) * Tt;
            g_scores[r0 + s]     = (t > s)     ? acc[mi][nj][0] : 0.f;
            g_scores[r0 + s + 1] = (t > s + 1) ? acc[mi][nj][1] : 0.f;
            g_scores[r1 + s]     = (t + 8 > s)     ? acc[mi][nj][2] : 0.f;
            g_scores[r1 + s + 1] = (t + 8 > s + 1) ? acc[mi][nj][3] : 0.f;
        }
}

// yKV = scores @ xs (causal K-extent)
__global__ __launch_bounds__(256, 2) void k_sv()
{
    int dtile = blockIdx.x, ttile = blockIdx.y, z = blockIdx.z;
    int b = z / NHh;
    const float* A  = g_scores + ((size_t)z * Tt + (size_t)ttile * BMT) * Tt;
    const float* Bm = g_xs + (size_t)b * Tt * Dd + dtile * BNT;
    float acc[4][4][4] = {};
    mma_tile128<false>(A, Tt, Bm, Dd, (ttile + 1) * BMT, acc);
    EPI_SETUP;
    #pragma unroll
    for (int mi = 0; mi < 4; mi++)
        #pragma unroll
        for (int nj = 0; nj < 4; nj++) {
            int t = ttile * BMT + am + mi * 16 + er;
            int d = dtile * BNT + bn + nj * 8 + ec;
            size_t r0 = ((size_t)z * Tt + t) * Dd;
            size_t r1 = ((size_t)z * Tt + t + 8) * Dd;
            g_ykv[r0 + d]     = acc[mi][nj][0];
            g_ykv[r0 + d + 1] = acc[mi][nj][1];
            g_ykv[r1 + d]     = acc[mi][nj][2];
            g_ykv[r1 + d + 1] = acc[mi][nj][3];
        }
}

__global__ __launch_bounds__(256) void k_ln_ykv()
{
    size_t row = blockIdx.x;
    float* p = g_ykv + row * 512;
    int t = threadIdx.x;
    float o0, o1;
    ln512_pair(p[t], p[t + 256], o0, o1);
    p[t] = o0;
    p[t + 256] = o1;
}

// y_sparse = relu(ln(yKV) @ encv[h]); xy = x_sparse * y_sparse -> [b,t,h,n]
__global__ __launch_bounds__(256, 2) void k_venc_mul(const float* __restrict__ encv)
{
    int z = blockIdx.z;
    int b = z / NHh, h = z % NHh;
    int n0 = blockIdx.x * BNT, m0 = blockIdx.y * BMT;
    const float* A  = g_ykv + (size_t)z * Tt * Dd + (size_t)m0 * Dd;
    const float* Bm = encv + (size_t)h * Dd * Nn + n0;
    float acc[4][4][4] = {};
    mma_tile128<false>(A, Dd, Bm, Nn, Dd, acc);
    EPI_SETUP;
    #pragma unroll
    for (int mi = 0; mi < 4; mi++)
        #pragma unroll
        for (int nj = 0; nj < 4; nj++) {
            int n = n0 + bn + nj * 8 + ec;
            #pragma unroll
            for (int hh = 0; hh < 2; hh++) {
                int t = m0 + am + mi * 16 + er + hh * 8;
                size_t src = ((size_t)z * Tt + t) * Nn + n;
                size_t dst = (((size_t)(b * Tt + t)) * NHh + h) * Nn + n;
                float y0 = fmaxf(acc[mi][nj][hh * 2], 0.f);
                float y1 = fmaxf(acc[mi][nj][hh * 2 + 1], 0.f);
                g_xy[dst]     = y0 * g_xsp[src];
                g_xy[dst + 1] = y1 * g_xsp[src + 1];
            }
        }
}

// yMLP = xy[4096,2048] @ decoder[2048,512] -> g_tmp
__global__ __launch_bounds__(256, 2) void k_dec(const float* __restrict__ decw)
{
    int n0 = blockIdx.x * BNT, m0 = blockIdx.y * BMT;
    float acc[4][4][4] = {};
    mma_tile128<false>(g_xy + (size_t)m0 * HN, HN, decw + n0, Dd, HN, acc);
    EPI_SETUP;
    #pragma unroll
    for (int mi = 0; mi < 4; mi++)
        #pragma unroll
        for (int nj = 0; nj < 4; nj++) {
            int m = m0 + am + mi * 16 + er;
            int n = n0 + bn + nj * 8 + ec;
            g_tmp[(size_t)m * Dd + n]           = acc[mi][nj][0];
            g_tmp[(size_t)m * Dd + n + 1]       = acc[mi][nj][1];
            g_tmp[(size_t)(m + 8) * Dd + n]     = acc[mi][nj][2];
            g_tmp[(size_t)(m + 8) * Dd + n + 1] = acc[mi][nj][3];
        }
}

__global__ __launch_bounds__(256) void k_resid_ln()
{
    size_t row = blockIdx.x;
    const float* a = g_xs + row * 512;
    const float* bp = g_tmp + row * 512;
    int t = threadIdx.x;
    float l0, l1;
    ln512_pair(bp[t], bp[t + 256], l0, l1);
    float t0 = a[t] + l0, t1 = a[t + 256] + l1;
    float o0, o1;
    ln512_pair(t0, t1, o0, o1);
    g_xs[row * 512 + t] = o0;
    g_xs[row * 512 + t + 256] = o1;
}

__global__ __launch_bounds__(256, 2) void k_head(
    const float* __restrict__ hw, const float* __restrict__ hb, float* __restrict__ out)
{
    int n0 = blockIdx.x * BNT, m0 = blockIdx.y * BMT;
    float acc[4][4][4] = {};
    mma_tile128<false>(g_xs + (size_t)m0 * Dd, Dd, hw + n0, Dd, Dd, acc);
    EPI_SETUP;
    #pragma unroll
    for (int mi = 0; mi < 4; mi++)
        #pragma unroll
        for (int nj = 0; nj < 4; nj++) {
            int m = m0 + am + mi * 16 + er;
            int n = n0 + bn + nj * 8 + ec;
            out[(size_t)m * Dd + n]           = acc[mi][nj][0] + hb[n];
            out[(size_t)m * Dd + n + 1]       = acc[mi][nj][1] + hb[n + 1];
            out[(size_t)(m + 8) * Dd + n]     = acc[mi][nj][2] + hb[n];
            out[(size_t)(m + 8) * Dd + n + 1] = acc[mi][nj][3] + hb[n + 1];
        }
}

// ---------------------------------------------------------------------------
extern "C" void kernel_launch(void* const* d_in, const int* in_sizes, int n_in,
                              void* d_out, int out_size)
{
    const float* x    = (const float*)d_in[0];
    const float* w_in = (const float*)d_in[1];
    const float* b_in = (const float*)d_in[2];
    const float* enc  = (const float*)d_in[3];
    const float* encv = (const float*)d_in[4];
    const float* dec  = (const float*)d_in[5];
    const float* hw   = (const float*)d_in[6];
    const float* hb   = (const float*)d_in[7];
    float* out = (float*)d_out;

    dim3 blk(256);

    k_inproj<<<dim3(Dd / BNT, BT / BMT), blk>>>(x, w_in, b_in);
    k_ln_inproj<<<BT, 256>>>();

    for (int layer = 0; layer < 3; layer++) {
        k_enc_rope<<<dim3(Nn / BNT, Tt / BMT, BH), blk>>>(enc);
        k_qk<<<dim3(Tt / BNT, Tt / BMT, BH), blk>>>();
        k_sv<<<dim3(Dd / BNT, Tt / BMT, BH), blk>>>();
        k_ln_ykv<<<BH * Tt, 256>>>();
        k_venc_mul<<<dim3(Nn / BNT, Tt / BMT, BH), blk>>>(encv);
        k_dec<<<dim3(Dd / BNT, BT / BMT), blk>>>(dec);
        k_resid_ln<<<BT, 256>>>();
    }

    k_head<<<dim3(Dd / BNT, BT / BMT), blk>>>(hw, hb, out);
}